// round 14
// baseline (speedup 1.0000x reference)
#include <cuda_runtime.h>
#include <math.h>

#define B_  32
#define L_  128
#define D_  300
#define H_  128
#define G4  512
#define E_  34
#define A_  36
#define NH  256
#define N_  4096    // B_*L_

// ---------------- scratch (device globals; no allocations) ----------------
__device__ float  d_xp2[2][N_][G4];        // [dir][n][gate-row]
__device__ float4 d_wt[2][32][G4];         // packed W_hh: [dir][k4][row]
__device__ float  d_hidden[N_*NH];         // [n][2H]
__device__ float  d_base[N_*A_];
__device__ float  d_trig[N_*A_];
__device__ int    d_evpred[N_];
__device__ int    d_dummy;

__device__ __forceinline__ float sigf(float x){ return 1.f/(1.f + __expf(-x)); }
__device__ __forceinline__ float tanhfast(float x){ return 2.f/(1.f + __expf(-2.f*x)) - 1.f; }

__device__ __forceinline__ void ffma2(unsigned long long &d, unsigned long long a, unsigned long long b){
    asm("fma.rn.f32x2 %0, %1, %2, %0;" : "+l"(d) : "l"(a), "l"(b));
}
__device__ __forceinline__ unsigned long long splat2(float a){
    unsigned long long d; asm("mov.b64 %0, {%1, %1};" : "=l"(d) : "f"(a)); return d;
}
__device__ __forceinline__ float2 unpack2(unsigned long long a){
    float2 r; asm("mov.b64 {%0, %1}, %2;" : "=f"(r.x), "=f"(r.y) : "l"(a)); return r;
}

struct __align__(16) ull2 { unsigned long long x, y; };

// ---------------- K0: pack W_hh into [dir][k4][row] float4 ----------------
__global__ void k0_pack(const float* __restrict__ whhf, const float* __restrict__ whhb){
    int idx = blockIdx.x*256 + threadIdx.x;
    if (idx >= 2*G4*32) return;
    int dir = idx >> 14;
    int rem = idx & 16383;
    int r   = rem >> 5;
    int k4  = rem & 31;
    const float* w = (dir ? whhb : whhf) + (size_t)r*H_ + k4*4;
    d_wt[dir][k4][r] = make_float4(w[0], w[1], w[2], w[3]);
}

// ---------------- Kdummy: launch-slot positioning ----------------
__global__ void kdummy(){ if (threadIdx.x == 0) d_dummy = 1; }

// ---------------- K1: emb gather + input projection SGEMM ----------------
// 128x128x8 tiles, 8x8 micro, f32x2, LDG double-buffer, 2 blocks/SM.
#define K1LOAD(K0_)                                                        \
    do {                                                                   \
        int kk_ = (K0_);                                                   \
        if (kk_ + lkh + 3 < D_){                                           \
            float4 a4 = *(const float4*)(a_src + kk_);                     \
            float4 b4 = *(const float4*)(b_src + kk_);                     \
            av[0]=a4.x; av[1]=a4.y; av[2]=a4.z; av[3]=a4.w;                \
            bv[0]=b4.x; bv[1]=b4.y; bv[2]=b4.z; bv[3]=b4.w;                \
        } else {                                                           \
            _Pragma("unroll")                                              \
            for (int u=0;u<4;u++){                                         \
                int k = kk_ + lkh + u;                                     \
                av[u] = (k < D_) ? a_src[kk_ + u] : 0.f;                   \
                bv[u] = (k < D_) ? b_src[kk_ + u] : 0.f;                   \
            }                                                              \
        }                                                                  \
    } while(0)

__global__ void __launch_bounds__(256, 2) k1_gemm(const int* __restrict__ ids, const float* __restrict__ emb,
                        const float* __restrict__ wf, const float* __restrict__ wb,
                        const float* __restrict__ bihf, const float* __restrict__ bhhf,
                        const float* __restrict__ bihb, const float* __restrict__ bhhb)
{
    __shared__ float As[8][132];
    __shared__ float Bs[8][132];
    int tid = threadIdx.x;
    int n0 = blockIdx.y * 128;
    int c0 = blockIdx.x * 128;
    int tx = tid & 15, ty = tid >> 4;

    int lrow = tid >> 1;
    int lkh  = (tid & 1) * 4;

    const float* a_src = emb + (size_t)ids[n0 + lrow] * D_ + lkh;
    int gcol = c0 + lrow;
    const float* b_src = ((gcol < 512) ? (wf + (size_t)gcol * D_)
                                       : (wb + (size_t)(gcol - 512) * D_)) + lkh;

    unsigned long long acc2[8][4];
    #pragma unroll
    for (int i=0;i<8;i++)
        #pragma unroll
        for (int p=0;p<4;p++) acc2[i][p]=0ull;

    float av[4], bv[4];
    K1LOAD(0);

    for (int k0 = 0; k0 < 304; k0 += 8){
        #pragma unroll
        for (int u=0;u<4;u++){ As[lkh+u][lrow] = av[u]; Bs[lkh+u][lrow] = bv[u]; }
        __syncthreads();
        if (k0 + 8 < 304) K1LOAD(k0 + 8);     // LDG in flight during compute
        #pragma unroll
        for (int k=0;k<8;k++){
            float4 a0 = *(const float4*)&As[k][ty*8];
            float4 a1 = *(const float4*)&As[k][ty*8+4];
            ull2 b0 = *(const ull2*)&Bs[k][tx*8];
            ull2 b1 = *(const ull2*)&Bs[k][tx*8+4];
            float af[8];
            af[0]=a0.x;af[1]=a0.y;af[2]=a0.z;af[3]=a0.w;
            af[4]=a1.x;af[5]=a1.y;af[6]=a1.z;af[7]=a1.w;
            #pragma unroll
            for (int i=0;i<8;i++){
                unsigned long long asp = splat2(af[i]);
                ffma2(acc2[i][0], asp, b0.x);
                ffma2(acc2[i][1], asp, b0.y);
                ffma2(acc2[i][2], asp, b1.x);
                ffma2(acc2[i][3], asp, b1.y);
            }
        }
        __syncthreads();
    }
    int colb = c0 + tx*8;
    int dir  = colb >> 9;
    int jb   = colb & 511;
    float bias[8];
    #pragma unroll
    for (int j=0;j<8;j++){
        int jj = jb + j;
        bias[j] = dir ? (bihb[jj]+bhhb[jj]) : (bihf[jj]+bhhf[jj]);
    }
    #pragma unroll
    for (int i=0;i<8;i++){
        int n = n0 + ty*8 + i;
        float* dst = &d_xp2[dir][n][jb];
        float2 p0 = unpack2(acc2[i][0]);
        float2 p1 = unpack2(acc2[i][1]);
        float2 p2 = unpack2(acc2[i][2]);
        float2 p3 = unpack2(acc2[i][3]);
        float4 v0 = make_float4(p0.x+bias[0], p0.y+bias[1], p1.x+bias[2], p1.y+bias[3]);
        float4 v1 = make_float4(p2.x+bias[4], p2.y+bias[5], p3.x+bias[6], p3.y+bias[7]);
        *(float4*)(dst)   = v0;
        *(float4*)(dst+4) = v1;
    }
}

// ---------------- K2: BiLSTM (round-7 best: 64 blocks x 256 thr, 20 reg-k4 + 12 SMEM-k4) ----------------
__global__ void __launch_bounds__(256, 1) k2_lstm()
{
    extern __shared__ float4 smemv[];
    float4* swB = smemv;                       // [12][512] : swB[k4*512 + r]
    float*  h_s = (float*)(swB + 12*512);      // [128]
    float*  ig_s= h_s + 128;                   // [128]

    int bid = blockIdx.x;
    int dir = bid >> 5;
    int b   = bid & 31;
    int t   = threadIdx.x;
    int r0  = t, r1 = t + 256;

    const ull2* wtd = (const ull2*)&d_wt[dir][0][0];   // [k4*512 + r]

    ull2 wr0[20], wr1[20];
    #pragma unroll
    for (int k4=0; k4<20; k4++){
        wr0[k4] = wtd[k4*512 + r0];
        wr1[k4] = wtd[k4*512 + r1];
    }
    for (int idx = t; idx < 12*512; idx += 256){
        swB[idx] = *(const float4*)&d_wt[dir][20 + (idx >> 9)][idx & 511];
    }
    if (t < 128) h_s[t] = 0.f;
    __syncthreads();

    const float* xpd = &d_xp2[dir][0][0];
    float cr = 0.f;
    int j = t - 128;
    bool low = (t < 128);

    for (int s = 0; s < L_; s++){
        int t_out = dir ? (L_-1 - s) : s;
        int n0 = b*L_ + t_out;
        float x0 = xpd[(size_t)n0*G4 + r0];
        float x1 = xpd[(size_t)n0*G4 + r1];

        unsigned long long a0=0ull, a1=0ull;
        #pragma unroll
        for (int k4=0; k4<20; k4++){
            ull2 h0 = *(const ull2*)(h_s + k4*4);
            ffma2(a0, wr0[k4].x, h0.x); ffma2(a0, wr0[k4].y, h0.y);
            ffma2(a1, wr1[k4].x, h0.x); ffma2(a1, wr1[k4].y, h0.y);
        }
        #pragma unroll
        for (int k4=0; k4<12; k4++){
            ull2 w0 = *(const ull2*)&swB[k4*512 + r0];
            ull2 w1 = *(const ull2*)&swB[k4*512 + r1];
            ull2 h0 = *(const ull2*)(h_s + 80 + k4*4);
            ffma2(a0, w0.x, h0.x); ffma2(a0, w0.y, h0.y);
            ffma2(a1, w1.x, h0.x); ffma2(a1, w1.y, h0.y);
        }
        float2 f0 = unpack2(a0), f1 = unpack2(a1);
        float z0 = f0.x + f0.y + x0;
        float z1 = f1.x + f1.y + x1;

        if (low){
            ig_s[t] = sigf(z0) * tanhfast(z1);   // sig(i)*tanh(g)
        }
        __syncthreads();
        if (!low){
            cr = sigf(z0)*cr + ig_s[j];          // c = sig(f)*c + ig
            float h = sigf(z1)*tanhfast(cr);     // h = sig(o)*tanh(c)
            h_s[j] = h;
            d_hidden[(size_t)n0*NH + dir*H_ + j] = h;
        }
        __syncthreads();
    }
}

// ---------------- K3: fused heads GEMM, single-stage SMEM + event argmax ----------------
__global__ void __launch_bounds__(256) k3_heads(const float* __restrict__ evw, const float* __restrict__ evb,
                         const float* __restrict__ argw, const float* __restrict__ argb,
                         float* __restrict__ out_ev)
{
    extern __shared__ float sm3[];
    float* hsT = sm3;              // [256][68]  hsT[k*68 + r]
    float* wT  = hsT + 256*68;     // [256][56]  wT[k*56 + cl]
    float* evs = wT + 256*56;      // [64][34]

    int rb = (blockIdx.x >> 1) * 64;
    int cg = blockIdx.x & 1;
    int cbase = cg * 53;
    int tid = threadIdx.x;
    int tx = tid & 15, ty = tid >> 4;

    {
        int r  = tid & 63;
        int kc = (tid >> 6) * 64;
        const float4* src = (const float4*)&d_hidden[(size_t)(rb+r)*NH + kc];
        #pragma unroll
        for (int m=0;m<16;m++){
            float4 v = src[m];
            int k = kc + m*4;
            hsT[(k+0)*68 + r] = v.x;
            hsT[(k+1)*68 + r] = v.y;
            hsT[(k+2)*68 + r] = v.z;
            hsT[(k+3)*68 + r] = v.w;
        }
    }
    {
        int cl = tid & 63;
        int kc = (tid >> 6) * 64;
        if (cl < 53){
            int c = cbase + cl;
            const float* srcp = (c < 34) ? (evw + (size_t)c*256)
                              : (c < 70) ? (argw + (size_t)(c-34)*545)
                                         : (argw + (size_t)(c-70)*545 + 256);
            #pragma unroll 8
            for (int m=0;m<64;m++){
                wT[(kc+m)*56 + cl] = __ldg(srcp + kc + m);
            }
        }
    }
    __syncthreads();

    unsigned long long acc[4][2];
    #pragma unroll
    for (int i=0;i<4;i++){ acc[i][0]=0ull; acc[i][1]=0ull; }

    #pragma unroll 4
    for (int k=0;k<256;k++){
        float4 hv = *(const float4*)&hsT[k*68 + ty*4];
        ull2   wv = *(const ull2*)&wT[k*56 + tx*4];
        unsigned long long h0 = splat2(hv.x);
        unsigned long long h1 = splat2(hv.y);
        unsigned long long h2 = splat2(hv.z);
        unsigned long long h3 = splat2(hv.w);
        ffma2(acc[0][0], h0, wv.x); ffma2(acc[0][1], h0, wv.y);
        ffma2(acc[1][0], h1, wv.x); ffma2(acc[1][1], h1, wv.y);
        ffma2(acc[2][0], h2, wv.x); ffma2(acc[2][1], h2, wv.y);
        ffma2(acc[3][0], h3, wv.x); ffma2(acc[3][1], h3, wv.y);
    }

    #pragma unroll
    for (int i=0;i<4;i++){
        int n = rb + ty*4 + i;
        float v[4];
        float2 p0 = unpack2(acc[i][0]);
        float2 p1 = unpack2(acc[i][1]);
        v[0]=p0.x; v[1]=p0.y; v[2]=p1.x; v[3]=p1.y;
        #pragma unroll
        for (int jj=0;jj<4;jj++){
            int cl = tx*4 + jj;
            if (cl < 53){
                int c = cbase + cl;
                if (c < 34){
                    float val = v[jj] + evb[c];
                    out_ev[(size_t)n*E_ + c] = val;
                    evs[(ty*4+i)*34 + c] = val;
                } else if (c < 70){
                    int a = c - 34;
                    d_base[(size_t)n*A_ + a] = v[jj] + argb[a];
                } else {
                    int a = c - 70;
                    d_trig[(size_t)n*A_ + a] = v[jj];
                }
            }
        }
    }
    if (cg == 0){
        __syncthreads();
        if (tid < 64){
            float best = evs[tid*34]; int bi = 0;
            #pragma unroll
            for (int e=1; e<E_; e++){ float vv = evs[tid*34 + e]; if (vv > best){ best = vv; bi = e; } }
            d_evpred[rb + tid] = bi;
        }
    }
}

// ---------------- K5: per-(b,l) g-scan + fused broadcast output (trig prefetch) ----------------
__global__ void k5_scan(const float* __restrict__ argw, float* __restrict__ out_args){
    __shared__ float w3[33][36];
    int bid = blockIdx.x;
    int b = bid >> 7, l = bid & 127;
    int lane = threadIdx.x;
    for (int i = lane; i < 33*36; i += 32){
        int c = i / 36, a = i % 36;
        w3[c][a] = argw[(size_t)a*545 + 512 + c];
    }
    __syncwarp();
    int a0 = lane, a1 = lane + 32;
    bool v1ok = (a1 < A_);
    float base0 = d_base[(b*L_+l)*A_ + a0];
    float base1 = v1ok ? d_base[(b*L_+l)*A_ + a1] : 0.f;
    float gt0 = 0.f, gt1 = 0.f;
    unsigned long long mask = 0ull;
    const float* trigb = d_trig + (size_t)b*L_*A_;
    float* outb = out_args + (size_t)b*L_*L_*A_ + (size_t)l*A_;
    const int* evp = d_evpred + b*L_;
    float t0 = trigb[a0];
    float t1 = v1ok ? trigb[a1] : 0.f;
    for (int i = 0; i < L_; i++){
        float t0c = t0, t1c = t1;
        if (i+1 < L_){
            t0 = trigb[(i+1)*A_ + a0];
            t1 = v1ok ? trigb[(i+1)*A_ + a1] : 0.f;
        }
        float v0 = base0 + t0c + gt0;
        float v1 = base1 + t1c + gt1;
        float* orow = outb + (size_t)i*L_*A_;
        orow[a0] = v0;
        if (v1ok) orow[a1] = v1;
        float bv; int bi2;
        if (v1ok && v1 > v0){ bv = v1; bi2 = a1; } else { bv = v0; bi2 = a0; }
        #pragma unroll
        for (int off=16; off; off>>=1){
            float ov = __shfl_xor_sync(0xffffffffu, bv, off);
            int   oi = __shfl_xor_sync(0xffffffffu, bi2, off);
            if (ov > bv || (ov == bv && oi < bi2)){ bv = ov; bi2 = oi; }
        }
        int ev = evp[i];
        if (ev > 0 && bi2 > 0){
            int c = ev - 1;
            unsigned long long bit = 1ull << c;
            if (!(mask & bit)){
                mask |= bit;
                gt0 += w3[c][a0];
                if (v1ok) gt1 += w3[c][a1];
            }
        }
    }
}

// ---------------- launch ----------------
extern "C" void kernel_launch(void* const* d_in, const int* in_sizes, int n_in,
                              void* d_out, int out_size)
{
    const int*   ids  = (const int*)d_in[0];
    const float* emb  = (const float*)d_in[1];
    const float* wihf = (const float*)d_in[2];
    const float* whhf = (const float*)d_in[3];
    const float* bihf = (const float*)d_in[4];
    const float* bhhf = (const float*)d_in[5];
    const float* wihb = (const float*)d_in[6];
    const float* whhb = (const float*)d_in[7];
    const float* bihb = (const float*)d_in[8];
    const float* bhhb = (const float*)d_in[9];
    const float* evw  = (const float*)d_in[10];
    const float* evb  = (const float*)d_in[11];
    const float* argw = (const float*)d_in[12];
    const float* argb = (const float*)d_in[13];
    float* out = (float*)d_out;

    const int k2_smem = 12*512*16 + 128*4 + 128*4;          // 99328
    const int k3_smem = (256*68 + 256*56 + 64*34) * 4;      // 135680
    cudaFuncSetAttribute(k2_lstm, cudaFuncAttributeMaxDynamicSharedMemorySize, k2_smem);
    cudaFuncSetAttribute(k3_heads, cudaFuncAttributeMaxDynamicSharedMemorySize, k3_smem);

    k0_pack<<<128, 256>>>(whhf, whhb);                       // launch 1
    kdummy<<<1, 32>>>();                                     // launch 2
    kdummy<<<1, 32>>>();                                     // launch 3
    dim3 g1(8, 32);
    k1_gemm<<<g1, 256>>>(ids, emb, wihf, wihb, bihf, bhhf, bihb, bhhb); // launch 4 -> ncu-profiled
    k2_lstm<<<64, 256, k2_smem>>>();
    k3_heads<<<128, 256, k3_smem>>>(evw, evb, argw, argb, out);
    k5_scan<<<N_, 32>>>(argw, out + N_*E_);
    (void)in_sizes; (void)n_in; (void)out_size;
}

// round 15
// speedup vs baseline: 1.6054x; 1.6054x over previous
#include <cuda_runtime.h>
#include <math.h>

#define B_  32
#define L_  128
#define D_  300
#define H_  128
#define G4  512
#define E_  34
#define A_  36
#define NH  256
#define N_  4096    // B_*L_

// ---------------- scratch (device globals; no allocations) ----------------
__device__ float  d_xp2[2][N_][G4];        // [dir][n][gate-row]
__device__ float4 d_wt[2][32][G4];         // packed W_hh: [dir][k4][row]
__device__ float  d_hidden[N_*NH];         // [n][2H]
__device__ float  d_base[N_*A_];
__device__ float  d_trig[N_*A_];
__device__ int    d_evpred[N_];
__device__ int    d_dummy;

__device__ __forceinline__ float sigf(float x){ return 1.f/(1.f + __expf(-x)); }
__device__ __forceinline__ float tanhfast(float x){ return 2.f/(1.f + __expf(-2.f*x)) - 1.f; }

__device__ __forceinline__ void ffma2(unsigned long long &d, unsigned long long a, unsigned long long b){
    asm("fma.rn.f32x2 %0, %1, %2, %0;" : "+l"(d) : "l"(a), "l"(b));
}
__device__ __forceinline__ unsigned long long splat2(float a){
    unsigned long long d; asm("mov.b64 %0, {%1, %1};" : "=l"(d) : "f"(a)); return d;
}
__device__ __forceinline__ float2 unpack2(unsigned long long a){
    float2 r; asm("mov.b64 {%0, %1}, %2;" : "=f"(r.x), "=f"(r.y) : "l"(a)); return r;
}

// NOTE: deliberately NOT __align__(16). Alignment forces 4-aligned register
// quads; in k2 (240 regs, 40 weight ull2s) that constraint caused spills
// (R14 k2 ~315us vs R7 139.6us). Plain 8B-aligned pairs allocate freely.
struct ull2 { unsigned long long x, y; };

// ---------------- K0: pack W_hh into [dir][k4][row] float4 ----------------
__global__ void k0_pack(const float* __restrict__ whhf, const float* __restrict__ whhb){
    int idx = blockIdx.x*256 + threadIdx.x;
    if (idx >= 2*G4*32) return;
    int dir = idx >> 14;
    int rem = idx & 16383;
    int r   = rem >> 5;
    int k4  = rem & 31;
    const float* w = (dir ? whhb : whhf) + (size_t)r*H_ + k4*4;
    d_wt[dir][k4][r] = make_float4(w[0], w[1], w[2], w[3]);
}

// ---------------- Kdummy: positions k2 into the ncu-profiled launch slot ----------------
__global__ void kdummy(){ if (threadIdx.x == 0) d_dummy = 1; }

// ---------------- K1: emb gather + input projection SGEMM ----------------
// 128x128x8 tiles, 8x8 micro, f32x2, LDG double-buffer, FULL register budget (1 block/SM).
#define K1LOAD(K0_)                                                        \
    do {                                                                   \
        int kk_ = (K0_);                                                   \
        if (kk_ + lkh + 3 < D_){                                           \
            float4 a4 = *(const float4*)(a_src + kk_);                     \
            float4 b4 = *(const float4*)(b_src + kk_);                     \
            av[0]=a4.x; av[1]=a4.y; av[2]=a4.z; av[3]=a4.w;                \
            bv[0]=b4.x; bv[1]=b4.y; bv[2]=b4.z; bv[3]=b4.w;                \
        } else {                                                           \
            _Pragma("unroll")                                              \
            for (int u=0;u<4;u++){                                         \
                int k = kk_ + lkh + u;                                     \
                av[u] = (k < D_) ? a_src[kk_ + u] : 0.f;                   \
                bv[u] = (k < D_) ? b_src[kk_ + u] : 0.f;                   \
            }                                                              \
        }                                                                  \
    } while(0)

__global__ void __launch_bounds__(256) k1_gemm(const int* __restrict__ ids, const float* __restrict__ emb,
                        const float* __restrict__ wf, const float* __restrict__ wb,
                        const float* __restrict__ bihf, const float* __restrict__ bhhf,
                        const float* __restrict__ bihb, const float* __restrict__ bhhb)
{
    __shared__ float As[8][132];
    __shared__ float Bs[8][132];
    int tid = threadIdx.x;
    int n0 = blockIdx.y * 128;
    int c0 = blockIdx.x * 128;
    int tx = tid & 15, ty = tid >> 4;

    int lrow = tid >> 1;
    int lkh  = (tid & 1) * 4;

    const float* a_src = emb + (size_t)ids[n0 + lrow] * D_ + lkh;
    int gcol = c0 + lrow;
    const float* b_src = ((gcol < 512) ? (wf + (size_t)gcol * D_)
                                       : (wb + (size_t)(gcol - 512) * D_)) + lkh;

    unsigned long long acc2[8][4];
    #pragma unroll
    for (int i=0;i<8;i++)
        #pragma unroll
        for (int p=0;p<4;p++) acc2[i][p]=0ull;

    float av[4], bv[4];
    K1LOAD(0);

    for (int k0 = 0; k0 < 304; k0 += 8){
        #pragma unroll
        for (int u=0;u<4;u++){ As[lkh+u][lrow] = av[u]; Bs[lkh+u][lrow] = bv[u]; }
        __syncthreads();
        if (k0 + 8 < 304) K1LOAD(k0 + 8);     // LDG in flight during compute
        #pragma unroll
        for (int k=0;k<8;k++){
            float4 a0 = *(const float4*)&As[k][ty*8];
            float4 a1 = *(const float4*)&As[k][ty*8+4];
            ull2 b0 = *(const ull2*)&Bs[k][tx*8];
            ull2 b1 = *(const ull2*)&Bs[k][tx*8+4];
            float af[8];
            af[0]=a0.x;af[1]=a0.y;af[2]=a0.z;af[3]=a0.w;
            af[4]=a1.x;af[5]=a1.y;af[6]=a1.z;af[7]=a1.w;
            #pragma unroll
            for (int i=0;i<8;i++){
                unsigned long long asp = splat2(af[i]);
                ffma2(acc2[i][0], asp, b0.x);
                ffma2(acc2[i][1], asp, b0.y);
                ffma2(acc2[i][2], asp, b1.x);
                ffma2(acc2[i][3], asp, b1.y);
            }
        }
        __syncthreads();
    }
    int colb = c0 + tx*8;
    int dir  = colb >> 9;
    int jb   = colb & 511;
    float bias[8];
    #pragma unroll
    for (int j=0;j<8;j++){
        int jj = jb + j;
        bias[j] = dir ? (bihb[jj]+bhhb[jj]) : (bihf[jj]+bhhf[jj]);
    }
    #pragma unroll
    for (int i=0;i<8;i++){
        int n = n0 + ty*8 + i;
        float* dst = &d_xp2[dir][n][jb];
        float2 p0 = unpack2(acc2[i][0]);
        float2 p1 = unpack2(acc2[i][1]);
        float2 p2 = unpack2(acc2[i][2]);
        float2 p3 = unpack2(acc2[i][3]);
        float4 v0 = make_float4(p0.x+bias[0], p0.y+bias[1], p1.x+bias[2], p1.y+bias[3]);
        float4 v1 = make_float4(p2.x+bias[4], p2.y+bias[5], p3.x+bias[6], p3.y+bias[7]);
        *(float4*)(dst)   = v0;
        *(float4*)(dst+4) = v1;
    }
}

// ---------------- K2: BiLSTM (round-7 best: 64 blocks x 256 thr, 20 reg-k4 + 12 SMEM-k4) ----------------
__global__ void __launch_bounds__(256, 1) k2_lstm()
{
    extern __shared__ float4 smemv[];
    float4* swB = smemv;                       // [12][512] : swB[k4*512 + r]
    float*  h_s = (float*)(swB + 12*512);      // [128]
    float*  ig_s= h_s + 128;                   // [128]

    int bid = blockIdx.x;
    int dir = bid >> 5;
    int b   = bid & 31;
    int t   = threadIdx.x;
    int r0  = t, r1 = t + 256;

    const ull2* wtd = (const ull2*)&d_wt[dir][0][0];   // [k4*512 + r]

    ull2 wr0[20], wr1[20];
    #pragma unroll
    for (int k4=0; k4<20; k4++){
        wr0[k4] = wtd[k4*512 + r0];
        wr1[k4] = wtd[k4*512 + r1];
    }
    for (int idx = t; idx < 12*512; idx += 256){
        swB[idx] = *(const float4*)&d_wt[dir][20 + (idx >> 9)][idx & 511];
    }
    if (t < 128) h_s[t] = 0.f;
    __syncthreads();

    const float* xpd = &d_xp2[dir][0][0];
    float cr = 0.f;
    int j = t - 128;
    bool low = (t < 128);

    for (int s = 0; s < L_; s++){
        int t_out = dir ? (L_-1 - s) : s;
        int n0 = b*L_ + t_out;
        float x0 = xpd[(size_t)n0*G4 + r0];
        float x1 = xpd[(size_t)n0*G4 + r1];

        unsigned long long a0=0ull, a1=0ull;
        #pragma unroll
        for (int k4=0; k4<20; k4++){
            ull2 h0 = *(const ull2*)(h_s + k4*4);
            ffma2(a0, wr0[k4].x, h0.x); ffma2(a0, wr0[k4].y, h0.y);
            ffma2(a1, wr1[k4].x, h0.x); ffma2(a1, wr1[k4].y, h0.y);
        }
        #pragma unroll
        for (int k4=0; k4<12; k4++){
            ull2 w0 = *(const ull2*)&swB[k4*512 + r0];
            ull2 w1 = *(const ull2*)&swB[k4*512 + r1];
            ull2 h0 = *(const ull2*)(h_s + 80 + k4*4);
            ffma2(a0, w0.x, h0.x); ffma2(a0, w0.y, h0.y);
            ffma2(a1, w1.x, h0.x); ffma2(a1, w1.y, h0.y);
        }
        float2 f0 = unpack2(a0), f1 = unpack2(a1);
        float z0 = f0.x + f0.y + x0;
        float z1 = f1.x + f1.y + x1;

        if (low){
            ig_s[t] = sigf(z0) * tanhfast(z1);   // sig(i)*tanh(g)
        }
        __syncthreads();
        if (!low){
            cr = sigf(z0)*cr + ig_s[j];          // c = sig(f)*c + ig
            float h = sigf(z1)*tanhfast(cr);     // h = sig(o)*tanh(c)
            h_s[j] = h;
            d_hidden[(size_t)n0*NH + dir*H_ + j] = h;
        }
        __syncthreads();
    }
}

// ---------------- K3: fused heads GEMM, single-stage SMEM + event argmax ----------------
__global__ void __launch_bounds__(256) k3_heads(const float* __restrict__ evw, const float* __restrict__ evb,
                         const float* __restrict__ argw, const float* __restrict__ argb,
                         float* __restrict__ out_ev)
{
    extern __shared__ float sm3[];
    float* hsT = sm3;              // [256][68]  hsT[k*68 + r]
    float* wT  = hsT + 256*68;     // [256][56]  wT[k*56 + cl]
    float* evs = wT + 256*56;      // [64][34]

    int rb = (blockIdx.x >> 1) * 64;
    int cg = blockIdx.x & 1;
    int cbase = cg * 53;
    int tid = threadIdx.x;
    int tx = tid & 15, ty = tid >> 4;

    {
        int r  = tid & 63;
        int kc = (tid >> 6) * 64;
        const float4* src = (const float4*)&d_hidden[(size_t)(rb+r)*NH + kc];
        #pragma unroll
        for (int m=0;m<16;m++){
            float4 v = src[m];
            int k = kc + m*4;
            hsT[(k+0)*68 + r] = v.x;
            hsT[(k+1)*68 + r] = v.y;
            hsT[(k+2)*68 + r] = v.z;
            hsT[(k+3)*68 + r] = v.w;
        }
    }
    {
        int cl = tid & 63;
        int kc = (tid >> 6) * 64;
        if (cl < 53){
            int c = cbase + cl;
            const float* srcp = (c < 34) ? (evw + (size_t)c*256)
                              : (c < 70) ? (argw + (size_t)(c-34)*545)
                                         : (argw + (size_t)(c-70)*545 + 256);
            #pragma unroll 8
            for (int m=0;m<64;m++){
                wT[(kc+m)*56 + cl] = __ldg(srcp + kc + m);
            }
        }
    }
    __syncthreads();

    unsigned long long acc[4][2];
    #pragma unroll
    for (int i=0;i<4;i++){ acc[i][0]=0ull; acc[i][1]=0ull; }

    #pragma unroll 4
    for (int k=0;k<256;k++){
        float4 hv = *(const float4*)&hsT[k*68 + ty*4];
        ull2   wv = *(const ull2*)&wT[k*56 + tx*4];
        unsigned long long h0 = splat2(hv.x);
        unsigned long long h1 = splat2(hv.y);
        unsigned long long h2 = splat2(hv.z);
        unsigned long long h3 = splat2(hv.w);
        ffma2(acc[0][0], h0, wv.x); ffma2(acc[0][1], h0, wv.y);
        ffma2(acc[1][0], h1, wv.x); ffma2(acc[1][1], h1, wv.y);
        ffma2(acc[2][0], h2, wv.x); ffma2(acc[2][1], h2, wv.y);
        ffma2(acc[3][0], h3, wv.x); ffma2(acc[3][1], h3, wv.y);
    }

    #pragma unroll
    for (int i=0;i<4;i++){
        int n = rb + ty*4 + i;
        float v[4];
        float2 p0 = unpack2(acc[i][0]);
        float2 p1 = unpack2(acc[i][1]);
        v[0]=p0.x; v[1]=p0.y; v[2]=p1.x; v[3]=p1.y;
        #pragma unroll
        for (int jj=0;jj<4;jj++){
            int cl = tx*4 + jj;
            if (cl < 53){
                int c = cbase + cl;
                if (c < 34){
                    float val = v[jj] + evb[c];
                    out_ev[(size_t)n*E_ + c] = val;
                    evs[(ty*4+i)*34 + c] = val;
                } else if (c < 70){
                    int a = c - 34;
                    d_base[(size_t)n*A_ + a] = v[jj] + argb[a];
                } else {
                    int a = c - 70;
                    d_trig[(size_t)n*A_ + a] = v[jj];
                }
            }
        }
    }
    if (cg == 0){
        __syncthreads();
        if (tid < 64){
            float best = evs[tid*34]; int bi = 0;
            #pragma unroll
            for (int e=1; e<E_; e++){ float vv = evs[tid*34 + e]; if (vv > best){ best = vv; bi = e; } }
            d_evpred[rb + tid] = bi;
        }
    }
}

// ---------------- K5: per-(b,l) g-scan + fused broadcast output (trig prefetch) ----------------
__global__ void k5_scan(const float* __restrict__ argw, float* __restrict__ out_args){
    __shared__ float w3[33][36];
    int bid = blockIdx.x;
    int b = bid >> 7, l = bid & 127;
    int lane = threadIdx.x;
    for (int i = lane; i < 33*36; i += 32){
        int c = i / 36, a = i % 36;
        w3[c][a] = argw[(size_t)a*545 + 512 + c];
    }
    __syncwarp();
    int a0 = lane, a1 = lane + 32;
    bool v1ok = (a1 < A_);
    float base0 = d_base[(b*L_+l)*A_ + a0];
    float base1 = v1ok ? d_base[(b*L_+l)*A_ + a1] : 0.f;
    float gt0 = 0.f, gt1 = 0.f;
    unsigned long long mask = 0ull;
    const float* trigb = d_trig + (size_t)b*L_*A_;
    float* outb = out_args + (size_t)b*L_*L_*A_ + (size_t)l*A_;
    const int* evp = d_evpred + b*L_;
    float t0 = trigb[a0];
    float t1 = v1ok ? trigb[a1] : 0.f;
    for (int i = 0; i < L_; i++){
        float t0c = t0, t1c = t1;
        if (i+1 < L_){
            t0 = trigb[(i+1)*A_ + a0];
            t1 = v1ok ? trigb[(i+1)*A_ + a1] : 0.f;
        }
        float v0 = base0 + t0c + gt0;
        float v1 = base1 + t1c + gt1;
        float* orow = outb + (size_t)i*L_*A_;
        orow[a0] = v0;
        if (v1ok) orow[a1] = v1;
        float bv; int bi2;
        if (v1ok && v1 > v0){ bv = v1; bi2 = a1; } else { bv = v0; bi2 = a0; }
        #pragma unroll
        for (int off=16; off; off>>=1){
            float ov = __shfl_xor_sync(0xffffffffu, bv, off);
            int   oi = __shfl_xor_sync(0xffffffffu, bi2, off);
            if (ov > bv || (ov == bv && oi < bi2)){ bv = ov; bi2 = oi; }
        }
        int ev = evp[i];
        if (ev > 0 && bi2 > 0){
            int c = ev - 1;
            unsigned long long bit = 1ull << c;
            if (!(mask & bit)){
                mask |= bit;
                gt0 += w3[c][a0];
                if (v1ok) gt1 += w3[c][a1];
            }
        }
    }
}

// ---------------- launch ----------------
extern "C" void kernel_launch(void* const* d_in, const int* in_sizes, int n_in,
                              void* d_out, int out_size)
{
    const int*   ids  = (const int*)d_in[0];
    const float* emb  = (const float*)d_in[1];
    const float* wihf = (const float*)d_in[2];
    const float* whhf = (const float*)d_in[3];
    const float* bihf = (const float*)d_in[4];
    const float* bhhf = (const float*)d_in[5];
    const float* wihb = (const float*)d_in[6];
    const float* whhb = (const float*)d_in[7];
    const float* bihb = (const float*)d_in[8];
    const float* bhhb = (const float*)d_in[9];
    const float* evw  = (const float*)d_in[10];
    const float* evb  = (const float*)d_in[11];
    const float* argw = (const float*)d_in[12];
    const float* argb = (const float*)d_in[13];
    float* out = (float*)d_out;

    const int k2_smem = 12*512*16 + 128*4 + 128*4;          // 99328
    const int k3_smem = (256*68 + 256*56 + 64*34) * 4;      // 135680
    cudaFuncSetAttribute(k2_lstm, cudaFuncAttributeMaxDynamicSharedMemorySize, k2_smem);
    cudaFuncSetAttribute(k3_heads, cudaFuncAttributeMaxDynamicSharedMemorySize, k3_smem);

    k0_pack<<<128, 256>>>(whhf, whhb);                       // launch 1
    dim3 g1(8, 32);
    k1_gemm<<<g1, 256>>>(ids, emb, wihf, wihb, bihf, bhhf, bihb, bhhb); // launch 2
    kdummy<<<1, 32>>>();                                     // launch 3 (positions k2 at slot 4)
    k2_lstm<<<64, 256, k2_smem>>>();                         // launch 4 -> ncu-profiled
    k3_heads<<<128, 256, k3_smem>>>(evw, evb, argw, argb, out);
    k5_scan<<<N_, 32>>>(argw, out + N_*E_);
    (void)in_sizes; (void)n_in; (void)out_size;
}

// round 16
// speedup vs baseline: 1.6666x; 1.0381x over previous
#include <cuda_runtime.h>
#include <math.h>

#define B_  32
#define L_  128
#define D_  300
#define H_  128
#define G4  512
#define E_  34
#define A_  36
#define NH  256
#define N_  4096    // B_*L_

// ---------------- scratch (device globals; no allocations) ----------------
__device__ float  d_xp2[2][N_][G4];        // [dir][n][gate-row]
__device__ float4 d_wt[2][32][G4];         // packed W_hh: [dir][k4][row]
__device__ float  d_hidden[N_*NH];         // [n][2H]
__device__ float  d_base[N_*A_];
__device__ float  d_trig[N_*A_];
__device__ int    d_evpred[N_];
__device__ int    d_dummy;

__device__ __forceinline__ float sigf(float x){ return 1.f/(1.f + __expf(-x)); }
__device__ __forceinline__ float tanhfast(float x){ return 2.f/(1.f + __expf(-2.f*x)) - 1.f; }

__device__ __forceinline__ void ffma2(unsigned long long &d, unsigned long long a, unsigned long long b){
    asm("fma.rn.f32x2 %0, %1, %2, %0;" : "+l"(d) : "l"(a), "l"(b));
}
__device__ __forceinline__ unsigned long long splat2(float a){
    unsigned long long d; asm("mov.b64 %0, {%1, %1};" : "=l"(d) : "f"(a)); return d;
}
__device__ __forceinline__ float2 unpack2(unsigned long long a){
    float2 r; asm("mov.b64 {%0, %1}, %2;" : "=f"(r.x), "=f"(r.y) : "l"(a)); return r;
}

// NOTE: deliberately NOT __align__(16) — alignment forces 4-aligned register
// quads and caused spills in k2 (R14). Plain 8B pairs allocate freely.
struct ull2 { unsigned long long x, y; };

__device__ __forceinline__ unsigned to_tf32(float x){
    unsigned u; asm("cvt.rna.tf32.f32 %0, %1;" : "=r"(u) : "f"(x)); return u;
}

#define MMA_TF32(c, a0,a1,a2,a3, b0,b1)                                        \
    asm volatile("mma.sync.aligned.m16n8k8.row.col.f32.tf32.tf32.f32 "         \
                 "{%0,%1,%2,%3}, {%4,%5,%6,%7}, {%8,%9}, {%0,%1,%2,%3};"       \
                 : "+f"((c)[0]), "+f"((c)[1]), "+f"((c)[2]), "+f"((c)[3])      \
                 : "r"(a0), "r"(a1), "r"(a2), "r"(a3), "r"(b0), "r"(b1))

// ---------------- K0: pack W_hh into [dir][k4][row] float4 ----------------
__global__ void k0_pack(const float* __restrict__ whhf, const float* __restrict__ whhb){
    int idx = blockIdx.x*256 + threadIdx.x;
    if (idx >= 2*G4*32) return;
    int dir = idx >> 14;
    int rem = idx & 16383;
    int r   = rem >> 5;
    int k4  = rem & 31;
    const float* w = (dir ? whhb : whhf) + (size_t)r*H_ + k4*4;
    d_wt[dir][k4][r] = make_float4(w[0], w[1], w[2], w[3]);
}

// ---------------- Kdummy: launch-slot positioning ----------------
__global__ void kdummy(){ if (threadIdx.x == 0) d_dummy = 1; }

// ---------------- K1: emb gather + input projection GEMM via tf32 tensor cores (3xTF32) ----------------
// 128x128 block tile, 8 warps (2 m x 4 n), warp = 64x32 (4x4 m16n8 frags), K-chunks of 8.
// Accuracy: hi/lo split, acc += hi*hi + hi*lo + lo*hi  (~fp32 quality).
#define K1LOAD(K0_)                                                        \
    do {                                                                   \
        int kk_ = (K0_);                                                   \
        if (kk_ + lkh + 3 < D_){                                           \
            float4 a4 = *(const float4*)(a_src + kk_);                     \
            float4 b4 = *(const float4*)(b_src + kk_);                     \
            av[0]=a4.x; av[1]=a4.y; av[2]=a4.z; av[3]=a4.w;                \
            bv[0]=b4.x; bv[1]=b4.y; bv[2]=b4.z; bv[3]=b4.w;                \
        } else {                                                           \
            _Pragma("unroll")                                              \
            for (int u=0;u<4;u++){                                         \
                int k = kk_ + lkh + u;                                     \
                av[u] = (k < D_) ? a_src[kk_ + u] : 0.f;                   \
                bv[u] = (k < D_) ? b_src[kk_ + u] : 0.f;                   \
            }                                                              \
        }                                                                  \
    } while(0)

__global__ void __launch_bounds__(256) k1_gemm(const int* __restrict__ ids, const float* __restrict__ emb,
                        const float* __restrict__ wf, const float* __restrict__ wb,
                        const float* __restrict__ bihf, const float* __restrict__ bhhf,
                        const float* __restrict__ bihb, const float* __restrict__ bhhb)
{
    __shared__ unsigned Ah[8][136], Al[8][136], Bh[8][136], Bl[8][136];
    int tid = threadIdx.x;
    int n0 = blockIdx.y * 128;
    int c0 = blockIdx.x * 128;
    int wid  = tid >> 5, lane = tid & 31;
    int wm = (wid & 1) * 64;        // warp m-offset
    int wn = (wid >> 1) * 32;       // warp n-offset

    int lrow = tid >> 1;            // 0..127
    int lkh  = (tid & 1) * 4;       // 0 or 4

    const float* a_src = emb + (size_t)ids[n0 + lrow] * D_ + lkh;
    int gcol = c0 + lrow;
    const float* b_src = ((gcol < 512) ? (wf + (size_t)gcol * D_)
                                       : (wb + (size_t)(gcol - 512) * D_)) + lkh;

    float acc[4][4][4];
    #pragma unroll
    for (int mi=0;mi<4;mi++)
        #pragma unroll
        for (int ni=0;ni<4;ni++)
            #pragma unroll
            for (int q=0;q<4;q++) acc[mi][ni][q]=0.f;

    float av[4], bv[4];
    K1LOAD(0);

    int ar = lane >> 2;             // fragment row/col helper
    int ak = lane & 3;

    for (int k0 = 0; k0 < 304; k0 += 8){
        // stage with fused hi/lo tf32 split
        #pragma unroll
        for (int u=0;u<4;u++){
            unsigned h = to_tf32(av[u]);
            float lo = av[u] - __uint_as_float(h);
            Ah[lkh+u][lrow] = h;
            Al[lkh+u][lrow] = to_tf32(lo);
            unsigned hb2 = to_tf32(bv[u]);
            float lob = bv[u] - __uint_as_float(hb2);
            Bh[lkh+u][lrow] = hb2;
            Bl[lkh+u][lrow] = to_tf32(lob);
        }
        __syncthreads();
        if (k0 + 8 < 304) K1LOAD(k0 + 8);     // next LDG in flight

        unsigned ah[4][4], al[4][4];
        #pragma unroll
        for (int mi=0;mi<4;mi++){
            int m = wm + mi*16 + ar;
            ah[mi][0] = Ah[ak  ][m];   ah[mi][1] = Ah[ak  ][m+8];
            ah[mi][2] = Ah[ak+4][m];   ah[mi][3] = Ah[ak+4][m+8];
            al[mi][0] = Al[ak  ][m];   al[mi][1] = Al[ak  ][m+8];
            al[mi][2] = Al[ak+4][m];   al[mi][3] = Al[ak+4][m+8];
        }
        #pragma unroll
        for (int ni=0;ni<4;ni++){
            int n = wn + ni*8 + ar;
            unsigned bh0 = Bh[ak][n], bh1 = Bh[ak+4][n];
            unsigned bl0 = Bl[ak][n], bl1 = Bl[ak+4][n];
            #pragma unroll
            for (int mi=0;mi<4;mi++){
                MMA_TF32(acc[mi][ni], ah[mi][0],ah[mi][1],ah[mi][2],ah[mi][3], bh0,bh1);
                MMA_TF32(acc[mi][ni], ah[mi][0],ah[mi][1],ah[mi][2],ah[mi][3], bl0,bl1);
                MMA_TF32(acc[mi][ni], al[mi][0],al[mi][1],al[mi][2],al[mi][3], bh0,bh1);
            }
        }
        __syncthreads();
    }

    // epilogue: c0/c1 at (row, 2c), (row, 2c+1); c2/c3 at row+8
    int er = lane >> 2;
    int ec = (lane & 3) * 2;
    #pragma unroll
    for (int ni=0;ni<4;ni++){
        int col_local = wn + ni*8 + ec;
        int gc  = c0 + col_local;
        int dir = gc >> 9;
        int jb  = gc & 511;
        float bias0 = dir ? (bihb[jb]+bhhb[jb])     : (bihf[jb]+bhhf[jb]);
        float bias1 = dir ? (bihb[jb+1]+bhhb[jb+1]) : (bihf[jb+1]+bhhf[jb+1]);
        #pragma unroll
        for (int mi=0;mi<4;mi++){
            int row0 = n0 + wm + mi*16 + er;
            int row1 = row0 + 8;
            float2 v0 = make_float2(acc[mi][ni][0]+bias0, acc[mi][ni][1]+bias1);
            float2 v1 = make_float2(acc[mi][ni][2]+bias0, acc[mi][ni][3]+bias1);
            *(float2*)&d_xp2[dir][row0][jb] = v0;
            *(float2*)&d_xp2[dir][row1][jb] = v1;
        }
    }
}

// ---------------- K2: BiLSTM (round-7 best: 64 blocks x 256 thr, 20 reg-k4 + 12 SMEM-k4) ----------------
__global__ void __launch_bounds__(256, 1) k2_lstm()
{
    extern __shared__ float4 smemv[];
    float4* swB = smemv;                       // [12][512] : swB[k4*512 + r]
    float*  h_s = (float*)(swB + 12*512);      // [128]
    float*  ig_s= h_s + 128;                   // [128]

    int bid = blockIdx.x;
    int dir = bid >> 5;
    int b   = bid & 31;
    int t   = threadIdx.x;
    int r0  = t, r1 = t + 256;

    const ull2* wtd = (const ull2*)&d_wt[dir][0][0];   // [k4*512 + r]

    ull2 wr0[20], wr1[20];
    #pragma unroll
    for (int k4=0; k4<20; k4++){
        wr0[k4] = wtd[k4*512 + r0];
        wr1[k4] = wtd[k4*512 + r1];
    }
    for (int idx = t; idx < 12*512; idx += 256){
        swB[idx] = *(const float4*)&d_wt[dir][20 + (idx >> 9)][idx & 511];
    }
    if (t < 128) h_s[t] = 0.f;
    __syncthreads();

    const float* xpd = &d_xp2[dir][0][0];
    float cr = 0.f;
    int j = t - 128;
    bool low = (t < 128);

    for (int s = 0; s < L_; s++){
        int t_out = dir ? (L_-1 - s) : s;
        int n0 = b*L_ + t_out;
        float x0 = xpd[(size_t)n0*G4 + r0];
        float x1 = xpd[(size_t)n0*G4 + r1];

        unsigned long long a0=0ull, a1=0ull;
        #pragma unroll
        for (int k4=0; k4<20; k4++){
            ull2 h0 = *(const ull2*)(h_s + k4*4);
            ffma2(a0, wr0[k4].x, h0.x); ffma2(a0, wr0[k4].y, h0.y);
            ffma2(a1, wr1[k4].x, h0.x); ffma2(a1, wr1[k4].y, h0.y);
        }
        #pragma unroll
        for (int k4=0; k4<12; k4++){
            ull2 w0 = *(const ull2*)&swB[k4*512 + r0];
            ull2 w1 = *(const ull2*)&swB[k4*512 + r1];
            ull2 h0 = *(const ull2*)(h_s + 80 + k4*4);
            ffma2(a0, w0.x, h0.x); ffma2(a0, w0.y, h0.y);
            ffma2(a1, w1.x, h0.x); ffma2(a1, w1.y, h0.y);
        }
        float2 f0 = unpack2(a0), f1 = unpack2(a1);
        float z0 = f0.x + f0.y + x0;
        float z1 = f1.x + f1.y + x1;

        if (low){
            ig_s[t] = sigf(z0) * tanhfast(z1);   // sig(i)*tanh(g)
        }
        __syncthreads();
        if (!low){
            cr = sigf(z0)*cr + ig_s[j];          // c = sig(f)*c + ig
            float h = sigf(z1)*tanhfast(cr);     // h = sig(o)*tanh(c)
            h_s[j] = h;
            d_hidden[(size_t)n0*NH + dir*H_ + j] = h;
        }
        __syncthreads();
    }
}

// ---------------- K3: fused heads GEMM, single-stage SMEM + event argmax ----------------
__global__ void __launch_bounds__(256) k3_heads(const float* __restrict__ evw, const float* __restrict__ evb,
                         const float* __restrict__ argw, const float* __restrict__ argb,
                         float* __restrict__ out_ev)
{
    extern __shared__ float sm3[];
    float* hsT = sm3;              // [256][68]  hsT[k*68 + r]
    float* wT  = hsT + 256*68;     // [256][56]  wT[k*56 + cl]
    float* evs = wT + 256*56;      // [64][34]

    int rb = (blockIdx.x >> 1) * 64;
    int cg = blockIdx.x & 1;
    int cbase = cg * 53;
    int tid = threadIdx.x;
    int tx = tid & 15, ty = tid >> 4;

    {
        int r  = tid & 63;
        int kc = (tid >> 6) * 64;
        const float4* src = (const float4*)&d_hidden[(size_t)(rb+r)*NH + kc];
        #pragma unroll
        for (int m=0;m<16;m++){
            float4 v = src[m];
            int k = kc + m*4;
            hsT[(k+0)*68 + r] = v.x;
            hsT[(k+1)*68 + r] = v.y;
            hsT[(k+2)*68 + r] = v.z;
            hsT[(k+3)*68 + r] = v.w;
        }
    }
    {
        int cl = tid & 63;
        int kc = (tid >> 6) * 64;
        if (cl < 53){
            int c = cbase + cl;
            const float* srcp = (c < 34) ? (evw + (size_t)c*256)
                              : (c < 70) ? (argw + (size_t)(c-34)*545)
                                         : (argw + (size_t)(c-70)*545 + 256);
            #pragma unroll 8
            for (int m=0;m<64;m++){
                wT[(kc+m)*56 + cl] = __ldg(srcp + kc + m);
            }
        }
    }
    __syncthreads();

    unsigned long long acc[4][2];
    #pragma unroll
    for (int i=0;i<4;i++){ acc[i][0]=0ull; acc[i][1]=0ull; }

    #pragma unroll 4
    for (int k=0;k<256;k++){
        float4 hv = *(const float4*)&hsT[k*68 + ty*4];
        ull2   wv = *(const ull2*)&wT[k*56 + tx*4];
        unsigned long long h0 = splat2(hv.x);
        unsigned long long h1 = splat2(hv.y);
        unsigned long long h2 = splat2(hv.z);
        unsigned long long h3 = splat2(hv.w);
        ffma2(acc[0][0], h0, wv.x); ffma2(acc[0][1], h0, wv.y);
        ffma2(acc[1][0], h1, wv.x); ffma2(acc[1][1], h1, wv.y);
        ffma2(acc[2][0], h2, wv.x); ffma2(acc[2][1], h2, wv.y);
        ffma2(acc[3][0], h3, wv.x); ffma2(acc[3][1], h3, wv.y);
    }

    #pragma unroll
    for (int i=0;i<4;i++){
        int n = rb + ty*4 + i;
        float v[4];
        float2 p0 = unpack2(acc[i][0]);
        float2 p1 = unpack2(acc[i][1]);
        v[0]=p0.x; v[1]=p0.y; v[2]=p1.x; v[3]=p1.y;
        #pragma unroll
        for (int jj=0;jj<4;jj++){
            int cl = tx*4 + jj;
            if (cl < 53){
                int c = cbase + cl;
                if (c < 34){
                    float val = v[jj] + evb[c];
                    out_ev[(size_t)n*E_ + c] = val;
                    evs[(ty*4+i)*34 + c] = val;
                } else if (c < 70){
                    int a = c - 34;
                    d_base[(size_t)n*A_ + a] = v[jj] + argb[a];
                } else {
                    int a = c - 70;
                    d_trig[(size_t)n*A_ + a] = v[jj];
                }
            }
        }
    }
    if (cg == 0){
        __syncthreads();
        if (tid < 64){
            float best = evs[tid*34]; int bi = 0;
            #pragma unroll
            for (int e=1; e<E_; e++){ float vv = evs[tid*34 + e]; if (vv > best){ best = vv; bi = e; } }
            d_evpred[rb + tid] = bi;
        }
    }
}

// ---------------- K5: per-(b,l) g-scan + fused broadcast output (trig prefetch) ----------------
__global__ void k5_scan(const float* __restrict__ argw, float* __restrict__ out_args){
    __shared__ float w3[33][36];
    int bid = blockIdx.x;
    int b = bid >> 7, l = bid & 127;
    int lane = threadIdx.x;
    for (int i = lane; i < 33*36; i += 32){
        int c = i / 36, a = i % 36;
        w3[c][a] = argw[(size_t)a*545 + 512 + c];
    }
    __syncwarp();
    int a0 = lane, a1 = lane + 32;
    bool v1ok = (a1 < A_);
    float base0 = d_base[(b*L_+l)*A_ + a0];
    float base1 = v1ok ? d_base[(b*L_+l)*A_ + a1] : 0.f;
    float gt0 = 0.f, gt1 = 0.f;
    unsigned long long mask = 0ull;
    const float* trigb = d_trig + (size_t)b*L_*A_;
    float* outb = out_args + (size_t)b*L_*L_*A_ + (size_t)l*A_;
    const int* evp = d_evpred + b*L_;
    float t0 = trigb[a0];
    float t1 = v1ok ? trigb[a1] : 0.f;
    for (int i = 0; i < L_; i++){
        float t0c = t0, t1c = t1;
        if (i+1 < L_){
            t0 = trigb[(i+1)*A_ + a0];
            t1 = v1ok ? trigb[(i+1)*A_ + a1] : 0.f;
        }
        float v0 = base0 + t0c + gt0;
        float v1 = base1 + t1c + gt1;
        float* orow = outb + (size_t)i*L_*A_;
        orow[a0] = v0;
        if (v1ok) orow[a1] = v1;
        float bv; int bi2;
        if (v1ok && v1 > v0){ bv = v1; bi2 = a1; } else { bv = v0; bi2 = a0; }
        #pragma unroll
        for (int off=16; off; off>>=1){
            float ov = __shfl_xor_sync(0xffffffffu, bv, off);
            int   oi = __shfl_xor_sync(0xffffffffu, bi2, off);
            if (ov > bv || (ov == bv && oi < bi2)){ bv = ov; bi2 = oi; }
        }
        int ev = evp[i];
        if (ev > 0 && bi2 > 0){
            int c = ev - 1;
            unsigned long long bit = 1ull << c;
            if (!(mask & bit)){
                mask |= bit;
                gt0 += w3[c][a0];
                if (v1ok) gt1 += w3[c][a1];
            }
        }
    }
}

// ---------------- launch ----------------
extern "C" void kernel_launch(void* const* d_in, const int* in_sizes, int n_in,
                              void* d_out, int out_size)
{
    const int*   ids  = (const int*)d_in[0];
    const float* emb  = (const float*)d_in[1];
    const float* wihf = (const float*)d_in[2];
    const float* whhf = (const float*)d_in[3];
    const float* bihf = (const float*)d_in[4];
    const float* bhhf = (const float*)d_in[5];
    const float* wihb = (const float*)d_in[6];
    const float* whhb = (const float*)d_in[7];
    const float* bihb = (const float*)d_in[8];
    const float* bhhb = (const float*)d_in[9];
    const float* evw  = (const float*)d_in[10];
    const float* evb  = (const float*)d_in[11];
    const float* argw = (const float*)d_in[12];
    const float* argb = (const float*)d_in[13];
    float* out = (float*)d_out;

    const int k2_smem = 12*512*16 + 128*4 + 128*4;          // 99328
    const int k3_smem = (256*68 + 256*56 + 64*34) * 4;      // 135680
    cudaFuncSetAttribute(k2_lstm, cudaFuncAttributeMaxDynamicSharedMemorySize, k2_smem);
    cudaFuncSetAttribute(k3_heads, cudaFuncAttributeMaxDynamicSharedMemorySize, k3_smem);

    k0_pack<<<128, 256>>>(whhf, whhb);                       // launch 1
    kdummy<<<1, 32>>>();                                     // launch 2
    kdummy<<<1, 32>>>();                                     // launch 3
    dim3 g1(8, 32);
    k1_gemm<<<g1, 256>>>(ids, emb, wihf, wihb, bihf, bhhf, bihb, bhhb); // launch 4 -> ncu-profiled
    k2_lstm<<<64, 256, k2_smem>>>();
    k3_heads<<<128, 256, k3_smem>>>(evw, evb, argw, argb, out);
    k5_scan<<<N_, 32>>>(argw, out + N_*E_);
    (void)in_sizes; (void)n_in; (void)out_size;
}